// round 2
// baseline (speedup 1.0000x reference)
#include <cuda_runtime.h>
#include <cuda_bf16.h>
#include <cstdint>
#include <cstddef>

// ---------------- problem constants ----------------
#define TT   16384      // tokens = 4*4096
#define DIN  1280
#define DOUT 3840
#define KK   1408       // 1280 (x) + 16 (shared) + 96 (routed) + 16 pad
#define HC   128        // H columns: 16 shared | 96 routed | 6 router | 10 pad

// ---------------- device scratch (no cudaMalloc allowed) ----------------
__device__ __align__(256) __nv_bfloat16 g_Ah[(size_t)TT * KK];
__device__ __align__(256) __nv_bfloat16 g_Al[(size_t)TT * KK];
__device__ __align__(256) __nv_bfloat16 g_Bh[(size_t)DOUT * KK];
__device__ __align__(256) __nv_bfloat16 g_Bl[(size_t)DOUT * KK];
__device__ __align__(256) __nv_bfloat16 g_W1h[HC * DIN];
__device__ __align__(256) __nv_bfloat16 g_W1l[HC * DIN];
__device__ __align__(256) float         g_H[(size_t)TT * HC];

// ---------------- helpers ----------------
__device__ __forceinline__ uint32_t s2u(const void* p) {
    return (uint32_t)__cvta_generic_to_shared(p);
}
__device__ __forceinline__ uint32_t swz(uint32_t o) { return o ^ ((o >> 3) & 0x70); }

__device__ __forceinline__ void cpa16(uint32_t dst, const void* src) {
    asm volatile("cp.async.cg.shared.global [%0], [%1], 16;\n" :: "r"(dst), "l"(src) : "memory");
}
__device__ __forceinline__ void cp_commit() {
    asm volatile("cp.async.commit_group;\n" ::: "memory");
}

__device__ __forceinline__ void ldsm4(uint32_t* r, uint32_t addr) {
    asm volatile("ldmatrix.sync.aligned.m8n8.x4.shared.b16 {%0,%1,%2,%3}, [%4];"
                 : "=r"(r[0]), "=r"(r[1]), "=r"(r[2]), "=r"(r[3]) : "r"(addr));
}

__device__ __forceinline__ void mma16816(float* c, const uint32_t* a, uint32_t b0, uint32_t b1) {
    asm volatile(
        "mma.sync.aligned.m16n8k16.row.col.f32.bf16.bf16.f32 "
        "{%0,%1,%2,%3}, {%4,%5,%6,%7}, {%8,%9}, {%0,%1,%2,%3};"
        : "+f"(c[0]), "+f"(c[1]), "+f"(c[2]), "+f"(c[3])
        : "r"(a[0]), "r"(a[1]), "r"(a[2]), "r"(a[3]), "r"(b0), "r"(b1));
}

__device__ __forceinline__ void split2(float v, __nv_bfloat16& h, __nv_bfloat16& l) {
    h = __float2bfloat16(v);
    l = __float2bfloat16(v - __bfloat162float(h));
}

// ---------------- prep kernels ----------------
// B matrix transposed to [DOUT rows][KK cols], hi/lo bf16 split.
__global__ void prep_B(const float* __restrict__ base_w,
                       const float* __restrict__ sw2,
                       const float* __restrict__ rw2) {
    __shared__ float tile[32][33];
    const int kt = blockIdx.x * 32;   // KK/32 = 44
    const int nt = blockIdx.y * 32;   // DOUT/32 = 120
    const int tx = threadIdx.x, ty = threadIdx.y;  // (32, 8)
    #pragma unroll
    for (int j = 0; j < 4; j++) {
        int k = kt + ty + j * 8;
        int n = nt + tx;
        float v;
        if (k < 1280)       v = base_w[(size_t)k * DOUT + n];
        else if (k < 1296)  v = sw2[(size_t)(k - 1280) * DOUT + n];
        else if (k < 1392)  v = rw2[(size_t)(k - 1296) * DOUT + n];
        else                v = 0.f;
        tile[ty + j * 8][tx] = v;
    }
    __syncthreads();
    #pragma unroll
    for (int j = 0; j < 4; j++) {
        int n = nt + ty + j * 8;
        int k = kt + tx;
        float v = tile[tx][ty + j * 8];
        __nv_bfloat16 h, l; split2(v, h, l);
        size_t o = (size_t)n * KK + k;
        g_Bh[o] = h; g_Bl[o] = l;
    }
}

// W1cat transposed: [HC rows][DIN cols]; rows 0-15 shared_w1, 16-111 routed_w1, 112-117 router_w
__global__ void prep_W1(const float* __restrict__ sw1,
                        const float* __restrict__ rw1,
                        const float* __restrict__ rtw) {
    int idx = blockIdx.x * blockDim.x + threadIdx.x;
    if (idx >= HC * DIN) return;
    int n = idx / DIN;       // output col of H
    int k = idx - n * DIN;
    float v;
    if (n < 16)        v = sw1[(size_t)k * 16 + n];
    else if (n < 112)  { int jr = n - 16; int e = jr >> 4; int r = jr & 15;
                         v = rw1[((size_t)e * DIN + k) * 16 + r]; }
    else if (n < 118)  v = rtw[(size_t)k * 6 + (n - 112)];
    else               v = 0.f;
    __nv_bfloat16 h, l; split2(v, h, l);
    g_W1h[idx] = h; g_W1l[idx] = l;
}

__global__ void split_x(const float* __restrict__ x) {
    int idx = blockIdx.x * blockDim.x + threadIdx.x;
    if (idx >= TT * DIN) return;
    int t = idx / DIN;
    int k = idx - t * DIN;
    __nv_bfloat16 h, l; split2(x[idx], h, l);
    size_t o = (size_t)t * KK + k;
    g_Ah[o] = h; g_Al[o] = l;
}

// gates + g columns (A cols 1280..1407)
__global__ void gate_kernel(const float* __restrict__ router_b) {
    int t = blockIdx.x * blockDim.x + threadIdx.x;
    if (t >= TT) return;
    const float* h = g_H + (size_t)t * HC;
    float gates[6];
    float mx = -1e30f;
    #pragma unroll
    for (int e = 0; e < 6; e++) { gates[e] = h[112 + e] + router_b[e]; mx = fmaxf(mx, gates[e]); }
    float s = 0.f;
    #pragma unroll
    for (int e = 0; e < 6; e++) { gates[e] = expf(gates[e] - mx); s += gates[e]; }
    float inv = 1.f / s;
    #pragma unroll
    for (int e = 0; e < 6; e++) gates[e] *= inv;
    float cw[6] = {0.f, 0.f, 0.f, 0.f, 0.f, 0.f};
    bool used[6] = {false, false, false, false, false, false};
    for (int k = 0; k < 3; k++) {
        int bi = 0; float bv = -1.f;
        #pragma unroll
        for (int e = 0; e < 6; e++)
            if (!used[e] && gates[e] > bv) { bv = gates[e]; bi = e; }
        used[bi] = true; cw[bi] = bv;
    }
    size_t base = (size_t)t * KK + 1280;
    #pragma unroll
    for (int j = 0; j < 16; j++) {
        __nv_bfloat16 hh, ll; split2(h[j], hh, ll);
        g_Ah[base + j] = hh; g_Al[base + j] = ll;
    }
    #pragma unroll
    for (int e = 0; e < 6; e++) {
        float w = cw[e];
        #pragma unroll
        for (int r = 0; r < 16; r++) {
            float v = w * h[16 + e * 16 + r];
            __nv_bfloat16 hh, ll; split2(v, hh, ll);
            g_Ah[base + 16 + e * 16 + r] = hh;
            g_Al[base + 16 + e * 16 + r] = ll;
        }
    }
    #pragma unroll
    for (int j = 112; j < 128; j++) {
        g_Ah[base + j] = __float2bfloat16(0.f);
        g_Al[base + j] = __float2bfloat16(0.f);
    }
}

// ---------------- bf16x3 HMMA GEMM ----------------
// C[BM=128, BN=128] per CTA, BK=64, 8 warps (warp tile 64x32), 2-stage cp.async.
// Accumulates Ah*Bh + Ah*Bl + Al*Bh in fp32 register fragments.
// Stage layout: Ah @0, Al @16K, Bh @32K, Bl @48K; stage stride 64K.
template <int KT, bool IS_G2>
__global__ __launch_bounds__(256, 1)
void gemm_k(const float* __restrict__ bias, float* __restrict__ Cout) {
    extern __shared__ __align__(1024) char smem[];
    const uint32_t sb = s2u(smem);
    const int tid = threadIdx.x;
    const int wid = tid >> 5;
    const int lane = tid & 31;
    const int m0 = blockIdx.y * 128;
    const int n0 = blockIdx.x * 128;
    const int LDB = IS_G2 ? KK : DIN;

    const __nv_bfloat16* Bh = IS_G2 ? g_Bh : g_W1h;
    const __nv_bfloat16* Bl = IS_G2 ? g_Bl : g_W1l;

    const int wr = wid >> 2;         // 0-1  -> m offset 64*wr
    const int wc = wid & 3;          // 0-3  -> n offset 32*wc
    const int m_warp = wr * 64;
    const int n_warp = wc * 32;

    // ldmatrix per-lane row/col pieces
    const int lm_row = lane & 15;
    const int lm_kg  = lane >> 4;    // 0/1 -> +8 elements = +16B granule

    // ---- cp.async tile loader ----
    auto load_tile = [&](int s, int it) {
        const int k0 = it * 64;
        const uint32_t st = sb + (uint32_t)s * 65536u;
        // A tiles (Ah, Al): 128 rows x 8 chunks
        #pragma unroll
        for (int r = 0; r < 4; r++) {
            int c = tid + r * 256;           // 0..1023
            int row = c >> 3, ch = c & 7;
            uint32_t d = swz((uint32_t)(row * 128 + ch * 16));
            size_t go = (size_t)(m0 + row) * KK + k0 + ch * 8;
            cpa16(st + d,          g_Ah + go);
            cpa16(st + 16384 + d,  g_Al + go);
        }
        // B tiles (Bh, Bl)
        #pragma unroll
        for (int r = 0; r < 4; r++) {
            int c = tid + r * 256;
            int row = c >> 3, ch = c & 7;
            uint32_t d = swz((uint32_t)(row * 128 + ch * 16));
            size_t go = (size_t)(n0 + row) * LDB + k0 + ch * 8;
            cpa16(st + 32768 + d,  Bh + go);
            cpa16(st + 49152 + d,  Bl + go);
        }
        cp_commit();
    };

    float acc[4][4][4];
    #pragma unroll
    for (int a = 0; a < 4; a++)
        #pragma unroll
        for (int b = 0; b < 4; b++)
            #pragma unroll
            for (int c = 0; c < 4; c++) acc[a][b][c] = 0.f;

    load_tile(0, 0);

    for (int i = 0; i < KT; i++) {
        const int buf = i & 1;
        if (i + 1 < KT) {
            load_tile(buf ^ 1, i + 1);
            asm volatile("cp.async.wait_group 1;" ::: "memory");
        } else {
            asm volatile("cp.async.wait_group 0;" ::: "memory");
        }
        __syncthreads();

        const uint32_t st = sb + (uint32_t)buf * 65536u;
        #pragma unroll
        for (int ks = 0; ks < 4; ks++) {          // 4 x k16 inside BK=64
            const int kg = ks * 2 + lm_kg;        // 16B granule index
            uint32_t ah[4][4], al[4][4];
            #pragma unroll
            for (int mt = 0; mt < 4; mt++) {
                uint32_t off = swz((uint32_t)((m_warp + mt * 16 + lm_row) * 128 + kg * 16));
                ldsm4(ah[mt], st + off);
                ldsm4(al[mt], st + 16384 + off);
            }
            uint32_t bh[2][4], bl[2][4];
            #pragma unroll
            for (int nh = 0; nh < 2; nh++) {
                uint32_t off = swz((uint32_t)((n_warp + nh * 16 + lm_row) * 128 + kg * 16));
                ldsm4(bh[nh], st + 32768 + off);
                ldsm4(bl[nh], st + 49152 + off);
            }
            #pragma unroll
            for (int mt = 0; mt < 4; mt++) {
                #pragma unroll
                for (int nt = 0; nt < 4; nt++) {
                    const int nh = nt >> 1, sub = nt & 1;
                    mma16816(acc[mt][nt], ah[mt], bh[nh][sub], bh[nh][sub + 2]);
                    mma16816(acc[mt][nt], ah[mt], bl[nh][sub], bl[nh][sub + 2]);
                    mma16816(acc[mt][nt], al[mt], bh[nh][sub], bh[nh][sub + 2]);
                }
            }
        }
        __syncthreads();
    }

    // ---- epilogue ----
    const int g  = lane >> 2;        // 0-7
    const int tg = lane & 3;         // 0-3
    #pragma unroll
    for (int mt = 0; mt < 4; mt++) {
        #pragma unroll
        for (int nt = 0; nt < 4; nt++) {
            int n = n0 + n_warp + nt * 8 + tg * 2;
            float b0 = 0.f, b1 = 0.f;
            if (IS_G2) { b0 = __ldg(bias + n); b1 = __ldg(bias + n + 1); }
            #pragma unroll
            for (int half = 0; half < 2; half++) {
                int m = m0 + m_warp + mt * 16 + g + half * 8;
                float2 v;
                v.x = acc[mt][nt][half * 2 + 0] + b0;
                v.y = acc[mt][nt][half * 2 + 1] + b1;
                if (IS_G2)
                    *reinterpret_cast<float2*>(Cout + (size_t)m * DOUT + n) = v;
                else
                    *reinterpret_cast<float2*>(g_H + (size_t)m * HC + (n - n0)) = v;
            }
        }
    }
}

// ---------------- host launcher ----------------
extern "C" void kernel_launch(void* const* d_in, const int* in_sizes, int n_in,
                              void* d_out, int out_size) {
    (void)in_sizes; (void)n_in; (void)out_size;
    const float* x         = (const float*)d_in[0];
    const float* base_w    = (const float*)d_in[1];
    const float* base_b    = (const float*)d_in[2];
    const float* shared_w1 = (const float*)d_in[3];
    const float* shared_w2 = (const float*)d_in[4];
    const float* routed_w1 = (const float*)d_in[5];
    const float* routed_w2 = (const float*)d_in[6];
    const float* router_w  = (const float*)d_in[7];
    const float* router_b  = (const float*)d_in[8];

    const int SMEM = 131072;  // 2 stages x 64KB
    cudaFuncSetAttribute(gemm_k<20, false>,
                         cudaFuncAttributeMaxDynamicSharedMemorySize, SMEM);
    cudaFuncSetAttribute(gemm_k<22, true>,
                         cudaFuncAttributeMaxDynamicSharedMemorySize, SMEM);

    prep_B<<<dim3(KK / 32, DOUT / 32), dim3(32, 8)>>>(base_w, shared_w2, routed_w2);
    prep_W1<<<(HC * DIN + 255) / 256, 256>>>(shared_w1, routed_w1, router_w);
    split_x<<<(TT * DIN + 255) / 256, 256>>>(x);
    // GEMM1: H[TT,128] = A[:, :1280] @ W1cat  (N = 128, K = 1280)
    gemm_k<20, false><<<dim3(1, TT / 128), 256, SMEM>>>(nullptr, nullptr);
    gate_kernel<<<(TT + 255) / 256, 256>>>(router_b);
    // GEMM2: out[TT, DOUT] = A[TT, KK] @ Bcat + bias
    gemm_k<22, true><<<dim3(DOUT / 128, TT / 128), 256, SMEM>>>(base_b, (float*)d_out);
}

// round 3
// speedup vs baseline: 1.3671x; 1.3671x over previous
#include <cuda_runtime.h>
#include <cuda_fp16.h>
#include <cstdint>
#include <cstddef>

// ---------------- problem constants ----------------
#define TT   16384      // tokens = 4*4096
#define DIN  1280
#define DOUT 3840
#define KK   1408       // 1280 (x) + 16 (shared) + 96 (routed) + 16 pad
#define HC   128        // H columns: 16 shared | 96 routed | 6 router | 10 pad

// ---------------- device scratch (no cudaMalloc allowed) ----------------
__device__ __align__(256) __half g_Ah[(size_t)TT * KK];
__device__ __align__(256) __half g_Al[(size_t)TT * KK];
__device__ __align__(256) __half g_B [(size_t)DOUT * KK];
__device__ __align__(256) __half g_W1[HC * DIN];
__device__ __align__(256) float  g_H [(size_t)TT * HC];

// ---------------- helpers ----------------
__device__ __forceinline__ uint32_t s2u(const void* p) {
    return (uint32_t)__cvta_generic_to_shared(p);
}
__device__ __forceinline__ uint32_t swz(uint32_t o) { return o ^ ((o >> 3) & 0x70); }

__device__ __forceinline__ void cpa16(uint32_t dst, const void* src) {
    asm volatile("cp.async.cg.shared.global [%0], [%1], 16;\n" :: "r"(dst), "l"(src) : "memory");
}
__device__ __forceinline__ void cp_commit() {
    asm volatile("cp.async.commit_group;\n" ::: "memory");
}

__device__ __forceinline__ void ldsm4(uint32_t* r, uint32_t addr) {
    asm volatile("ldmatrix.sync.aligned.m8n8.x4.shared.b16 {%0,%1,%2,%3}, [%4];"
                 : "=r"(r[0]), "=r"(r[1]), "=r"(r[2]), "=r"(r[3]) : "r"(addr));
}

__device__ __forceinline__ void mma16816(float* c, const uint32_t* a, uint32_t b0, uint32_t b1) {
    asm volatile(
        "mma.sync.aligned.m16n8k16.row.col.f32.f16.f16.f32 "
        "{%0,%1,%2,%3}, {%4,%5,%6,%7}, {%8,%9}, {%0,%1,%2,%3};"
        : "+f"(c[0]), "+f"(c[1]), "+f"(c[2]), "+f"(c[3])
        : "r"(a[0]), "r"(a[1]), "r"(a[2]), "r"(a[3]), "r"(b0), "r"(b1));
}

__device__ __forceinline__ void split2(float v, __half& h, __half& l) {
    h = __float2half(v);
    l = __float2half(v - __half2float(h));
}

// ---------------- prep kernels ----------------
// B matrix transposed to [DOUT rows][KK cols], fp16.
__global__ void prep_B(const float* __restrict__ base_w,
                       const float* __restrict__ sw2,
                       const float* __restrict__ rw2) {
    __shared__ float tile[32][33];
    const int kt = blockIdx.x * 32;   // KK/32 = 44
    const int nt = blockIdx.y * 32;   // DOUT/32 = 120
    const int tx = threadIdx.x, ty = threadIdx.y;  // (32, 8)
    #pragma unroll
    for (int j = 0; j < 4; j++) {
        int k = kt + ty + j * 8;
        int n = nt + tx;
        float v;
        if (k < 1280)       v = base_w[(size_t)k * DOUT + n];
        else if (k < 1296)  v = sw2[(size_t)(k - 1280) * DOUT + n];
        else if (k < 1392)  v = rw2[(size_t)(k - 1296) * DOUT + n];
        else                v = 0.f;
        tile[ty + j * 8][tx] = v;
    }
    __syncthreads();
    #pragma unroll
    for (int j = 0; j < 4; j++) {
        int n = nt + ty + j * 8;
        int k = kt + tx;
        g_B[(size_t)n * KK + k] = __float2half(tile[tx][ty + j * 8]);
    }
}

// W1cat transposed: [HC rows][DIN cols]; rows 0-15 shared_w1, 16-111 routed_w1, 112-117 router_w
__global__ void prep_W1(const float* __restrict__ sw1,
                        const float* __restrict__ rw1,
                        const float* __restrict__ rtw) {
    int idx = blockIdx.x * blockDim.x + threadIdx.x;
    if (idx >= HC * DIN) return;
    int n = idx / DIN;       // output col of H
    int k = idx - n * DIN;
    float v;
    if (n < 16)        v = sw1[(size_t)k * 16 + n];
    else if (n < 112)  { int jr = n - 16; int e = jr >> 4; int r = jr & 15;
                         v = rw1[((size_t)e * DIN + k) * 16 + r]; }
    else if (n < 118)  v = rtw[(size_t)k * 6 + (n - 112)];
    else               v = 0.f;
    g_W1[idx] = __float2half(v);
}

__global__ void split_x(const float* __restrict__ x) {
    int idx = blockIdx.x * blockDim.x + threadIdx.x;
    if (idx >= TT * DIN) return;
    int t = idx / DIN;
    int k = idx - t * DIN;
    __half h, l; split2(x[idx], h, l);
    size_t o = (size_t)t * KK + k;
    g_Ah[o] = h; g_Al[o] = l;
}

// gates + g columns (A cols 1280..1407)
__global__ void gate_kernel(const float* __restrict__ router_b) {
    int t = blockIdx.x * blockDim.x + threadIdx.x;
    if (t >= TT) return;
    const float* h = g_H + (size_t)t * HC;
    float gates[6];
    float mx = -1e30f;
    #pragma unroll
    for (int e = 0; e < 6; e++) { gates[e] = h[112 + e] + router_b[e]; mx = fmaxf(mx, gates[e]); }
    float s = 0.f;
    #pragma unroll
    for (int e = 0; e < 6; e++) { gates[e] = expf(gates[e] - mx); s += gates[e]; }
    float inv = 1.f / s;
    #pragma unroll
    for (int e = 0; e < 6; e++) gates[e] *= inv;
    float cw[6] = {0.f, 0.f, 0.f, 0.f, 0.f, 0.f};
    bool used[6] = {false, false, false, false, false, false};
    for (int k = 0; k < 3; k++) {
        int bi = 0; float bv = -1.f;
        #pragma unroll
        for (int e = 0; e < 6; e++)
            if (!used[e] && gates[e] > bv) { bv = gates[e]; bi = e; }
        used[bi] = true; cw[bi] = bv;
    }
    size_t base = (size_t)t * KK + 1280;
    #pragma unroll
    for (int j = 0; j < 16; j++) {
        __half hh, ll; split2(h[j], hh, ll);
        g_Ah[base + j] = hh; g_Al[base + j] = ll;
    }
    #pragma unroll
    for (int e = 0; e < 6; e++) {
        float w = cw[e];
        #pragma unroll
        for (int r = 0; r < 16; r++) {
            __half hh, ll; split2(w * h[16 + e * 16 + r], hh, ll);
            g_Ah[base + 16 + e * 16 + r] = hh;
            g_Al[base + 16 + e * 16 + r] = ll;
        }
    }
    #pragma unroll
    for (int j = 112; j < 128; j++) {
        g_Ah[base + j] = __float2half(0.f);
        g_Al[base + j] = __float2half(0.f);
    }
}

// ---------------- fp16x2 HMMA GEMM ----------------
// C[BM=128, BN=128] per CTA, BK=64, 8 warps (warp tile 64x32), 2-stage cp.async.
// Accumulates Ah*B + Al*B in fp32 register fragments.
// Stage layout: Ah @0, Al @16K, B @32K; stage stride 48K.
template <int KT, bool IS_G2>
__global__ __launch_bounds__(256, 1)
void gemm_k(const float* __restrict__ bias, float* __restrict__ Cout) {
    extern __shared__ __align__(1024) char smem[];
    const uint32_t sb = s2u(smem);
    const int tid = threadIdx.x;
    const int wid = tid >> 5;
    const int lane = tid & 31;
    const int m0 = blockIdx.y * 128;
    const int n0 = blockIdx.x * 128;
    const int LDB = IS_G2 ? KK : DIN;

    const __half* Bp = IS_G2 ? g_B : g_W1;

    const int wr = wid >> 2;         // 0-1  -> m offset 64*wr
    const int wc = wid & 3;          // 0-3  -> n offset 32*wc
    const int m_warp = wr * 64;
    const int n_warp = wc * 32;

    const int lm_row = lane & 15;
    const int lm_kg  = lane >> 4;    // 0/1 -> +16B granule

    auto load_tile = [&](int s, int it) {
        const int k0 = it * 64;
        const uint32_t st = sb + (uint32_t)s * 49152u;
        #pragma unroll
        for (int r = 0; r < 4; r++) {
            int c = tid + r * 256;           // 0..1023
            int row = c >> 3, ch = c & 7;
            uint32_t d = swz((uint32_t)(row * 128 + ch * 16));
            size_t go = (size_t)(m0 + row) * KK + k0 + ch * 8;
            cpa16(st + d,          g_Ah + go);
            cpa16(st + 16384 + d,  g_Al + go);
        }
        #pragma unroll
        for (int r = 0; r < 4; r++) {
            int c = tid + r * 256;
            int row = c >> 3, ch = c & 7;
            uint32_t d = swz((uint32_t)(row * 128 + ch * 16));
            size_t go = (size_t)(n0 + row) * LDB + k0 + ch * 8;
            cpa16(st + 32768 + d,  Bp + go);
        }
        cp_commit();
    };

    float acc[4][4][4];
    #pragma unroll
    for (int a = 0; a < 4; a++)
        #pragma unroll
        for (int b = 0; b < 4; b++)
            #pragma unroll
            for (int c = 0; c < 4; c++) acc[a][b][c] = 0.f;

    load_tile(0, 0);

    for (int i = 0; i < KT; i++) {
        const int buf = i & 1;
        if (i + 1 < KT) {
            load_tile(buf ^ 1, i + 1);
            asm volatile("cp.async.wait_group 1;" ::: "memory");
        } else {
            asm volatile("cp.async.wait_group 0;" ::: "memory");
        }
        __syncthreads();

        const uint32_t st = sb + (uint32_t)buf * 49152u;
        #pragma unroll
        for (int ks = 0; ks < 4; ks++) {          // 4 x k16 inside BK=64
            const int kg = ks * 2 + lm_kg;        // 16B granule index
            uint32_t ah[4][4], al[4][4];
            #pragma unroll
            for (int mt = 0; mt < 4; mt++) {
                uint32_t off = swz((uint32_t)((m_warp + mt * 16 + lm_row) * 128 + kg * 16));
                ldsm4(ah[mt], st + off);
                ldsm4(al[mt], st + 16384 + off);
            }
            uint32_t bb[2][4];
            #pragma unroll
            for (int nh = 0; nh < 2; nh++) {
                uint32_t off = swz((uint32_t)((n_warp + nh * 16 + lm_row) * 128 + kg * 16));
                ldsm4(bb[nh], st + 32768 + off);
            }
            // term 1: Ah*B — 16 independent accumulators back-to-back
            #pragma unroll
            for (int mt = 0; mt < 4; mt++)
                #pragma unroll
                for (int nt = 0; nt < 4; nt++) {
                    const int nh = nt >> 1, sub = nt & 1;
                    mma16816(acc[mt][nt], ah[mt], bb[nh][sub], bb[nh][sub + 2]);
                }
            // term 2: Al*B
            #pragma unroll
            for (int mt = 0; mt < 4; mt++)
                #pragma unroll
                for (int nt = 0; nt < 4; nt++) {
                    const int nh = nt >> 1, sub = nt & 1;
                    mma16816(acc[mt][nt], al[mt], bb[nh][sub], bb[nh][sub + 2]);
                }
        }
        __syncthreads();
    }

    // ---- epilogue ----
    const int g  = lane >> 2;        // 0-7
    const int tg = lane & 3;         // 0-3
    #pragma unroll
    for (int mt = 0; mt < 4; mt++) {
        #pragma unroll
        for (int nt = 0; nt < 4; nt++) {
            int n = n0 + n_warp + nt * 8 + tg * 2;
            float b0 = 0.f, b1 = 0.f;
            if (IS_G2) { b0 = __ldg(bias + n); b1 = __ldg(bias + n + 1); }
            #pragma unroll
            for (int half = 0; half < 2; half++) {
                int m = m0 + m_warp + mt * 16 + g + half * 8;
                float2 v;
                v.x = acc[mt][nt][half * 2 + 0] + b0;
                v.y = acc[mt][nt][half * 2 + 1] + b1;
                if (IS_G2)
                    *reinterpret_cast<float2*>(Cout + (size_t)m * DOUT + n) = v;
                else
                    *reinterpret_cast<float2*>(g_H + (size_t)m * HC + (n - n0)) = v;
            }
        }
    }
}

// ---------------- host launcher ----------------
extern "C" void kernel_launch(void* const* d_in, const int* in_sizes, int n_in,
                              void* d_out, int out_size) {
    (void)in_sizes; (void)n_in; (void)out_size;
    const float* x         = (const float*)d_in[0];
    const float* base_w    = (const float*)d_in[1];
    const float* base_b    = (const float*)d_in[2];
    const float* shared_w1 = (const float*)d_in[3];
    const float* shared_w2 = (const float*)d_in[4];
    const float* routed_w1 = (const float*)d_in[5];
    const float* routed_w2 = (const float*)d_in[6];
    const float* router_w  = (const float*)d_in[7];
    const float* router_b  = (const float*)d_in[8];

    const int SMEM = 98304;  // 2 stages x 48KB
    cudaFuncSetAttribute(gemm_k<20, false>,
                         cudaFuncAttributeMaxDynamicSharedMemorySize, SMEM);
    cudaFuncSetAttribute(gemm_k<22, true>,
                         cudaFuncAttributeMaxDynamicSharedMemorySize, SMEM);

    prep_B<<<dim3(KK / 32, DOUT / 32), dim3(32, 8)>>>(base_w, shared_w2, routed_w2);
    prep_W1<<<(HC * DIN + 255) / 256, 256>>>(shared_w1, routed_w1, router_w);
    split_x<<<(TT * DIN + 255) / 256, 256>>>(x);
    // GEMM1: H[TT,128] = A[:, :1280] @ W1cat  (N = 128, K = 1280)
    gemm_k<20, false><<<dim3(1, TT / 128), 256, SMEM>>>(nullptr, nullptr);
    gate_kernel<<<(TT + 255) / 256, 256>>>(router_b);
    // GEMM2: out[TT, DOUT] = A[TT, KK] @ Bcat + bias
    gemm_k<22, true><<<dim3(DOUT / 128, TT / 128), 256, SMEM>>>(base_b, (float*)d_out);
}

// round 4
// speedup vs baseline: 1.6009x; 1.1710x over previous
#include <cuda_runtime.h>
#include <cuda_fp16.h>
#include <cstdint>
#include <cstddef>

// ---------------- problem constants ----------------
#define TT   16384      // tokens = 4*4096
#define DIN  1280
#define DOUT 3840
#define KK   1408       // 1280 (x) + 16 (shared) + 96 (routed) + 16 pad
#define HC   128        // H columns: 16 shared | 96 routed | 6 router | 10 pad

// ---------------- device scratch (no cudaMalloc allowed) ----------------
__device__ __align__(256) __half g_Ah[(size_t)TT * KK];
__device__ __align__(256) __half g_Al[(size_t)TT * KK];
__device__ __align__(256) __half g_B [(size_t)DOUT * KK];
__device__ __align__(256) __half g_W1[HC * DIN];
__device__ __align__(256) float  g_H [(size_t)TT * HC];

// ---------------- helpers ----------------
__device__ __forceinline__ uint32_t s2u(const void* p) {
    return (uint32_t)__cvta_generic_to_shared(p);
}
__device__ __forceinline__ uint32_t swz(uint32_t o) { return o ^ ((o >> 3) & 0x70); }

__device__ __forceinline__ void cpa16(uint32_t dst, const void* src) {
    asm volatile("cp.async.cg.shared.global [%0], [%1], 16;\n" :: "r"(dst), "l"(src) : "memory");
}
__device__ __forceinline__ void cp_commit() {
    asm volatile("cp.async.commit_group;\n" ::: "memory");
}

__device__ __forceinline__ void ldsm4(uint32_t* r, uint32_t addr) {
    asm volatile("ldmatrix.sync.aligned.m8n8.x4.shared.b16 {%0,%1,%2,%3}, [%4];"
                 : "=r"(r[0]), "=r"(r[1]), "=r"(r[2]), "=r"(r[3]) : "r"(addr));
}

__device__ __forceinline__ void mma16816(float* c, const uint32_t* a, uint32_t b0, uint32_t b1) {
    asm volatile(
        "mma.sync.aligned.m16n8k16.row.col.f32.f16.f16.f32 "
        "{%0,%1,%2,%3}, {%4,%5,%6,%7}, {%8,%9}, {%0,%1,%2,%3};"
        : "+f"(c[0]), "+f"(c[1]), "+f"(c[2]), "+f"(c[3])
        : "r"(a[0]), "r"(a[1]), "r"(a[2]), "r"(a[3]), "r"(b0), "r"(b1));
}

__device__ __forceinline__ void split2(float v, __half& h, __half& l) {
    h = __float2half(v);
    l = __float2half(v - __half2float(h));
}

// ---------------- prep kernels ----------------
__global__ void prep_B(const float* __restrict__ base_w,
                       const float* __restrict__ sw2,
                       const float* __restrict__ rw2) {
    __shared__ float tile[32][33];
    const int kt = blockIdx.x * 32;
    const int nt = blockIdx.y * 32;
    const int tx = threadIdx.x, ty = threadIdx.y;  // (32, 8)
    #pragma unroll
    for (int j = 0; j < 4; j++) {
        int k = kt + ty + j * 8;
        int n = nt + tx;
        float v;
        if (k < 1280)       v = base_w[(size_t)k * DOUT + n];
        else if (k < 1296)  v = sw2[(size_t)(k - 1280) * DOUT + n];
        else if (k < 1392)  v = rw2[(size_t)(k - 1296) * DOUT + n];
        else                v = 0.f;
        tile[ty + j * 8][tx] = v;
    }
    __syncthreads();
    #pragma unroll
    for (int j = 0; j < 4; j++) {
        int n = nt + ty + j * 8;
        int k = kt + tx;
        g_B[(size_t)n * KK + k] = __float2half(tile[tx][ty + j * 8]);
    }
}

__global__ void prep_W1(const float* __restrict__ sw1,
                        const float* __restrict__ rw1,
                        const float* __restrict__ rtw) {
    int idx = blockIdx.x * blockDim.x + threadIdx.x;
    if (idx >= HC * DIN) return;
    int n = idx / DIN;
    int k = idx - n * DIN;
    float v;
    if (n < 16)        v = sw1[(size_t)k * 16 + n];
    else if (n < 112)  { int jr = n - 16; int e = jr >> 4; int r = jr & 15;
                         v = rw1[((size_t)e * DIN + k) * 16 + r]; }
    else if (n < 118)  v = rtw[(size_t)k * 6 + (n - 112)];
    else               v = 0.f;
    g_W1[idx] = __float2half(v);
}

__global__ void split_x(const float* __restrict__ x) {
    int idx = blockIdx.x * blockDim.x + threadIdx.x;
    if (idx >= TT * DIN) return;
    int t = idx / DIN;
    int k = idx - t * DIN;
    __half h, l; split2(x[idx], h, l);
    size_t o = (size_t)t * KK + k;
    g_Ah[o] = h; g_Al[o] = l;
}

__global__ void gate_kernel(const float* __restrict__ router_b) {
    int t = blockIdx.x * blockDim.x + threadIdx.x;
    if (t >= TT) return;
    const float* h = g_H + (size_t)t * HC;
    float gates[6];
    float mx = -1e30f;
    #pragma unroll
    for (int e = 0; e < 6; e++) { gates[e] = h[112 + e] + router_b[e]; mx = fmaxf(mx, gates[e]); }
    float s = 0.f;
    #pragma unroll
    for (int e = 0; e < 6; e++) { gates[e] = expf(gates[e] - mx); s += gates[e]; }
    float inv = 1.f / s;
    #pragma unroll
    for (int e = 0; e < 6; e++) gates[e] *= inv;
    float cw[6] = {0.f, 0.f, 0.f, 0.f, 0.f, 0.f};
    bool used[6] = {false, false, false, false, false, false};
    for (int k = 0; k < 3; k++) {
        int bi = 0; float bv = -1.f;
        #pragma unroll
        for (int e = 0; e < 6; e++)
            if (!used[e] && gates[e] > bv) { bv = gates[e]; bi = e; }
        used[bi] = true; cw[bi] = bv;
    }
    size_t base = (size_t)t * KK + 1280;
    #pragma unroll
    for (int j = 0; j < 16; j++) {
        __half hh, ll; split2(h[j], hh, ll);
        g_Ah[base + j] = hh; g_Al[base + j] = ll;
    }
    #pragma unroll
    for (int e = 0; e < 6; e++) {
        float w = cw[e];
        #pragma unroll
        for (int r = 0; r < 16; r++) {
            __half hh, ll; split2(w * h[16 + e * 16 + r], hh, ll);
            g_Ah[base + 16 + e * 16 + r] = hh;
            g_Al[base + 16 + e * 16 + r] = ll;
        }
    }
    #pragma unroll
    for (int j = 112; j < 128; j++) {
        g_Ah[base + j] = __float2half(0.f);
        g_Al[base + j] = __float2half(0.f);
    }
}

// ---------------- fp16x2 HMMA GEMM ----------------
// C[BM=128, BN=128] per CTA, BK=64, 8 warps (warp tile 64x32), 2-stage cp.async.
// 2 CTAs per SM (reg-dieted to <=128 regs) for latency hiding.
// Stage layout: Ah @0, Al @16K, B @32K; stage stride 48K.
template <int KT, bool IS_G2>
__global__ __launch_bounds__(256, 2)
void gemm_k(const float* __restrict__ bias, float* __restrict__ Cout) {
    extern __shared__ __align__(1024) char smem[];
    const uint32_t sb = s2u(smem);
    const int tid = threadIdx.x;
    const int wid = tid >> 5;
    const int lane = tid & 31;
    const int m0 = blockIdx.y * 128;
    const int n0 = blockIdx.x * 128;
    const int LDB = IS_G2 ? KK : DIN;

    const __half* Bp = IS_G2 ? g_B : g_W1;

    const int wr = wid >> 2;         // 0-1  -> m offset 64*wr
    const int wc = wid & 3;          // 0-3  -> n offset 32*wc
    const int m_warp = wr * 64;
    const int n_warp = wc * 32;

    const int lm_row = lane & 15;
    const int lm_kg  = lane >> 4;    // 0/1 -> +16B granule

    auto load_tile = [&](int s, int it) {
        const int k0 = it * 64;
        const uint32_t st = sb + (uint32_t)s * 49152u;
        #pragma unroll
        for (int r = 0; r < 4; r++) {
            int c = tid + r * 256;           // 0..1023
            int row = c >> 3, ch = c & 7;
            uint32_t d = swz((uint32_t)(row * 128 + ch * 16));
            size_t go = (size_t)(m0 + row) * KK + k0 + ch * 8;
            cpa16(st + d,          g_Ah + go);
            cpa16(st + 16384 + d,  g_Al + go);
        }
        #pragma unroll
        for (int r = 0; r < 4; r++) {
            int c = tid + r * 256;
            int row = c >> 3, ch = c & 7;
            uint32_t d = swz((uint32_t)(row * 128 + ch * 16));
            size_t go = (size_t)(n0 + row) * LDB + k0 + ch * 8;
            cpa16(st + 32768 + d,  Bp + go);
        }
        cp_commit();
    };

    float acc[4][4][4];
    #pragma unroll
    for (int a = 0; a < 4; a++)
        #pragma unroll
        for (int b = 0; b < 4; b++)
            #pragma unroll
            for (int c = 0; c < 4; c++) acc[a][b][c] = 0.f;

    load_tile(0, 0);

    for (int i = 0; i < KT; i++) {
        const int buf = i & 1;
        if (i + 1 < KT) {
            load_tile(buf ^ 1, i + 1);
            asm volatile("cp.async.wait_group 1;" ::: "memory");
        } else {
            asm volatile("cp.async.wait_group 0;" ::: "memory");
        }
        __syncthreads();

        const uint32_t st = sb + (uint32_t)buf * 49152u;
        #pragma unroll
        for (int ks = 0; ks < 4; ks++) {          // 4 x k16 inside BK=64
            const int kg = ks * 2 + lm_kg;        // 16B granule index
            uint32_t bb[2][4];
            #pragma unroll
            for (int nh = 0; nh < 2; nh++) {
                uint32_t off = swz((uint32_t)((n_warp + nh * 16 + lm_row) * 128 + kg * 16));
                ldsm4(bb[nh], st + 32768 + off);
            }
            // A fragments processed in two m-halves to cut live registers
            #pragma unroll
            for (int mh = 0; mh < 2; mh++) {
                uint32_t ah[2][4], al[2][4];
                #pragma unroll
                for (int q = 0; q < 2; q++) {
                    int mt = mh * 2 + q;
                    uint32_t off = swz((uint32_t)((m_warp + mt * 16 + lm_row) * 128 + kg * 16));
                    ldsm4(ah[q], st + off);
                    ldsm4(al[q], st + 16384 + off);
                }
                #pragma unroll
                for (int q = 0; q < 2; q++)
                    #pragma unroll
                    for (int nt = 0; nt < 4; nt++) {
                        const int nh = nt >> 1, sub = nt & 1;
                        mma16816(acc[mh * 2 + q][nt], ah[q], bb[nh][sub], bb[nh][sub + 2]);
                    }
                #pragma unroll
                for (int q = 0; q < 2; q++)
                    #pragma unroll
                    for (int nt = 0; nt < 4; nt++) {
                        const int nh = nt >> 1, sub = nt & 1;
                        mma16816(acc[mh * 2 + q][nt], al[q], bb[nh][sub], bb[nh][sub + 2]);
                    }
            }
        }
        __syncthreads();
    }

    // ---- epilogue ----
    const int g  = lane >> 2;        // 0-7
    const int tg = lane & 3;         // 0-3
    #pragma unroll
    for (int mt = 0; mt < 4; mt++) {
        #pragma unroll
        for (int nt = 0; nt < 4; nt++) {
            int n = n0 + n_warp + nt * 8 + tg * 2;
            float b0 = 0.f, b1 = 0.f;
            if (IS_G2) { b0 = __ldg(bias + n); b1 = __ldg(bias + n + 1); }
            #pragma unroll
            for (int half = 0; half < 2; half++) {
                int m = m0 + m_warp + mt * 16 + g + half * 8;
                float2 v;
                v.x = acc[mt][nt][half * 2 + 0] + b0;
                v.y = acc[mt][nt][half * 2 + 1] + b1;
                if (IS_G2)
                    *reinterpret_cast<float2*>(Cout + (size_t)m * DOUT + n) = v;
                else
                    *reinterpret_cast<float2*>(g_H + (size_t)m * HC + (n - n0)) = v;
            }
        }
    }
}

// ---------------- host launcher ----------------
extern "C" void kernel_launch(void* const* d_in, const int* in_sizes, int n_in,
                              void* d_out, int out_size) {
    (void)in_sizes; (void)n_in; (void)out_size;
    const float* x         = (const float*)d_in[0];
    const float* base_w    = (const float*)d_in[1];
    const float* base_b    = (const float*)d_in[2];
    const float* shared_w1 = (const float*)d_in[3];
    const float* shared_w2 = (const float*)d_in[4];
    const float* routed_w1 = (const float*)d_in[5];
    const float* routed_w2 = (const float*)d_in[6];
    const float* router_w  = (const float*)d_in[7];
    const float* router_b  = (const float*)d_in[8];

    const int SMEM = 98304;  // 2 stages x 48KB
    cudaFuncSetAttribute(gemm_k<20, false>,
                         cudaFuncAttributeMaxDynamicSharedMemorySize, SMEM);
    cudaFuncSetAttribute(gemm_k<22, true>,
                         cudaFuncAttributeMaxDynamicSharedMemorySize, SMEM);

    prep_B<<<dim3(KK / 32, DOUT / 32), dim3(32, 8)>>>(base_w, shared_w2, routed_w2);
    prep_W1<<<(HC * DIN + 255) / 256, 256>>>(shared_w1, routed_w1, router_w);
    split_x<<<(TT * DIN + 255) / 256, 256>>>(x);
    // GEMM1: H[TT,128] = A[:, :1280] @ W1cat  (N = 128, K = 1280)
    gemm_k<20, false><<<dim3(1, TT / 128), 256, SMEM>>>(nullptr, nullptr);
    gate_kernel<<<(TT + 255) / 256, 256>>>(router_b);
    // GEMM2: out[TT, DOUT] = A[TT, KK] @ Bcat + bias
    gemm_k<22, true><<<dim3(DOUT / 128, TT / 128), 256, SMEM>>>(base_b, (float*)d_out);
}

// round 5
// speedup vs baseline: 2.4770x; 1.5472x over previous
#include <cuda_runtime.h>
#include <cuda_fp16.h>
#include <cstdint>
#include <cstddef>

// ---------------- problem constants ----------------
#define TT   16384      // tokens = 4*4096
#define DIN  1280
#define DOUT 3840
#define KK   1408       // 1280 (x) + 16 (shared) + 96 (routed) + 16 pad
#define HC   128        // H columns: 16 shared | 96 routed | 6 router | 10 pad

// ---------------- device scratch (no cudaMalloc allowed) ----------------
__device__ __align__(256) __half g_Ah[(size_t)TT * KK];
__device__ __align__(256) __half g_Al[(size_t)TT * KK];
__device__ __align__(256) __half g_B [(size_t)DOUT * KK];
__device__ __align__(256) __half g_W1[HC * DIN];
__device__ __align__(256) float  g_H [(size_t)TT * HC];

// ---------------- helpers ----------------
__device__ __forceinline__ uint32_t s2u(const void* p) {
    return (uint32_t)__cvta_generic_to_shared(p);
}
__device__ __forceinline__ uint32_t swz(uint32_t o) { return o ^ ((o >> 3) & 0x70); }

__device__ __forceinline__ void cpa16(uint32_t dst, const void* src) {
    asm volatile("cp.async.cg.shared.global [%0], [%1], 16;\n" :: "r"(dst), "l"(src) : "memory");
}
__device__ __forceinline__ void cp_commit() {
    asm volatile("cp.async.commit_group;\n" ::: "memory");
}

__device__ __forceinline__ void ldsm4(uint32_t* r, uint32_t addr) {
    asm volatile("ldmatrix.sync.aligned.m8n8.x4.shared.b16 {%0,%1,%2,%3}, [%4];"
                 : "=r"(r[0]), "=r"(r[1]), "=r"(r[2]), "=r"(r[3]) : "r"(addr));
}

__device__ __forceinline__ void mma16816(float* c, const uint32_t* a, uint32_t b0, uint32_t b1) {
    asm volatile(
        "mma.sync.aligned.m16n8k16.row.col.f32.f16.f16.f32 "
        "{%0,%1,%2,%3}, {%4,%5,%6,%7}, {%8,%9}, {%0,%1,%2,%3};"
        : "+f"(c[0]), "+f"(c[1]), "+f"(c[2]), "+f"(c[3])
        : "r"(a[0]), "r"(a[1]), "r"(a[2]), "r"(a[3]), "r"(b0), "r"(b1));
}

__device__ __forceinline__ void split2(float v, __half& h, __half& l) {
    h = __float2half(v);
    l = __float2half(v - __half2float(h));
}

// ---------------- prep kernels ----------------
__global__ void prep_B(const float* __restrict__ base_w,
                       const float* __restrict__ sw2,
                       const float* __restrict__ rw2) {
    __shared__ float tile[32][33];
    const int kt = blockIdx.x * 32;
    const int nt = blockIdx.y * 32;
    const int tx = threadIdx.x, ty = threadIdx.y;  // (32, 8)
    #pragma unroll
    for (int j = 0; j < 4; j++) {
        int k = kt + ty + j * 8;
        int n = nt + tx;
        float v;
        if (k < 1280)       v = base_w[(size_t)k * DOUT + n];
        else if (k < 1296)  v = sw2[(size_t)(k - 1280) * DOUT + n];
        else if (k < 1392)  v = rw2[(size_t)(k - 1296) * DOUT + n];
        else                v = 0.f;
        tile[ty + j * 8][tx] = v;
    }
    __syncthreads();
    #pragma unroll
    for (int j = 0; j < 4; j++) {
        int n = nt + ty + j * 8;
        int k = kt + tx;
        g_B[(size_t)n * KK + k] = __float2half(tile[tx][ty + j * 8]);
    }
}

__global__ void prep_W1(const float* __restrict__ sw1,
                        const float* __restrict__ rw1,
                        const float* __restrict__ rtw) {
    int idx = blockIdx.x * blockDim.x + threadIdx.x;
    if (idx >= HC * DIN) return;
    int n = idx / DIN;
    int k = idx - n * DIN;
    float v;
    if (n < 16)        v = sw1[(size_t)k * 16 + n];
    else if (n < 112)  { int jr = n - 16; int e = jr >> 4; int r = jr & 15;
                         v = rw1[((size_t)e * DIN + k) * 16 + r]; }
    else if (n < 118)  v = rtw[(size_t)k * 6 + (n - 112)];
    else               v = 0.f;
    g_W1[idx] = __float2half(v);
}

__global__ void split_x(const float* __restrict__ x) {
    int idx = blockIdx.x * blockDim.x + threadIdx.x;
    if (idx >= TT * DIN) return;
    int t = idx / DIN;
    int k = idx - t * DIN;
    __half h, l; split2(x[idx], h, l);
    size_t o = (size_t)t * KK + k;
    g_Ah[o] = h; g_Al[o] = l;
}

__global__ void gate_kernel(const float* __restrict__ router_b) {
    int t = blockIdx.x * blockDim.x + threadIdx.x;
    if (t >= TT) return;
    const float* h = g_H + (size_t)t * HC;
    float gates[6];
    float mx = -1e30f;
    #pragma unroll
    for (int e = 0; e < 6; e++) { gates[e] = h[112 + e] + router_b[e]; mx = fmaxf(mx, gates[e]); }
    float s = 0.f;
    #pragma unroll
    for (int e = 0; e < 6; e++) { gates[e] = expf(gates[e] - mx); s += gates[e]; }
    float inv = 1.f / s;
    #pragma unroll
    for (int e = 0; e < 6; e++) gates[e] *= inv;
    float cw[6] = {0.f, 0.f, 0.f, 0.f, 0.f, 0.f};
    bool used[6] = {false, false, false, false, false, false};
    for (int k = 0; k < 3; k++) {
        int bi = 0; float bv = -1.f;
        #pragma unroll
        for (int e = 0; e < 6; e++)
            if (!used[e] && gates[e] > bv) { bv = gates[e]; bi = e; }
        used[bi] = true; cw[bi] = bv;
    }
    size_t base = (size_t)t * KK + 1280;
    #pragma unroll
    for (int j = 0; j < 16; j++)
        g_Ah[base + j] = __float2half(h[j]);
    #pragma unroll
    for (int e = 0; e < 6; e++) {
        float w = cw[e];
        #pragma unroll
        for (int r = 0; r < 16; r++)
            g_Ah[base + 16 + e * 16 + r] = __float2half(w * h[16 + e * 16 + r]);
    }
    #pragma unroll
    for (int j = 112; j < 128; j++)
        g_Ah[base + j] = __float2half(0.f);
}

// ---------------- GEMM1: fp16x2 (Ah+Al) @ W1, BM=128, BN=128, BK=64 ----------------
// Stage layout: Ah @0, Al @16K, B @32K; stage stride 48K. 2 stages.
__global__ __launch_bounds__(256, 2)
void gemm1_k() {
    constexpr int KT = 20;
    extern __shared__ __align__(1024) char smem[];
    const uint32_t sb = s2u(smem);
    const int tid = threadIdx.x;
    const int wid = tid >> 5;
    const int lane = tid & 31;
    const int m0 = blockIdx.y * 128;

    const int wr = wid >> 2;
    const int wc = wid & 3;
    const int m_warp = wr * 64;
    const int n_warp = wc * 32;
    const int lm_row = lane & 15;
    const int lm_kg  = lane >> 4;

    auto load_tile = [&](int s, int it) {
        const int k0 = it * 64;
        const uint32_t st = sb + (uint32_t)s * 49152u;
        #pragma unroll
        for (int r = 0; r < 4; r++) {
            int c = tid + r * 256;
            int row = c >> 3, ch = c & 7;
            uint32_t d = swz((uint32_t)(row * 128 + ch * 16));
            size_t go = (size_t)(m0 + row) * KK + k0 + ch * 8;
            cpa16(st + d,          g_Ah + go);
            cpa16(st + 16384 + d,  g_Al + go);
        }
        #pragma unroll
        for (int r = 0; r < 4; r++) {
            int c = tid + r * 256;
            int row = c >> 3, ch = c & 7;
            uint32_t d = swz((uint32_t)(row * 128 + ch * 16));
            size_t go = (size_t)row * DIN + k0 + ch * 8;
            cpa16(st + 32768 + d,  g_W1 + go);
        }
        cp_commit();
    };

    float acc[4][4][4];
    #pragma unroll
    for (int a = 0; a < 4; a++)
        #pragma unroll
        for (int b = 0; b < 4; b++)
            #pragma unroll
            for (int c = 0; c < 4; c++) acc[a][b][c] = 0.f;

    load_tile(0, 0);

    for (int i = 0; i < KT; i++) {
        const int buf = i & 1;
        if (i + 1 < KT) {
            load_tile(buf ^ 1, i + 1);
            asm volatile("cp.async.wait_group 1;" ::: "memory");
        } else {
            asm volatile("cp.async.wait_group 0;" ::: "memory");
        }
        __syncthreads();

        const uint32_t st = sb + (uint32_t)buf * 49152u;
        #pragma unroll
        for (int ks = 0; ks < 4; ks++) {
            const int kg = ks * 2 + lm_kg;
            uint32_t bb[2][4];
            #pragma unroll
            for (int nh = 0; nh < 2; nh++) {
                uint32_t off = swz((uint32_t)((n_warp + nh * 16 + lm_row) * 128 + kg * 16));
                ldsm4(bb[nh], st + 32768 + off);
            }
            #pragma unroll
            for (int mh = 0; mh < 2; mh++) {
                uint32_t ah[2][4], al[2][4];
                #pragma unroll
                for (int q = 0; q < 2; q++) {
                    int mt = mh * 2 + q;
                    uint32_t off = swz((uint32_t)((m_warp + mt * 16 + lm_row) * 128 + kg * 16));
                    ldsm4(ah[q], st + off);
                    ldsm4(al[q], st + 16384 + off);
                }
                #pragma unroll
                for (int q = 0; q < 2; q++)
                    #pragma unroll
                    for (int nt = 0; nt < 4; nt++) {
                        const int nh = nt >> 1, sub = nt & 1;
                        mma16816(acc[mh * 2 + q][nt], ah[q], bb[nh][sub], bb[nh][sub + 2]);
                    }
                #pragma unroll
                for (int q = 0; q < 2; q++)
                    #pragma unroll
                    for (int nt = 0; nt < 4; nt++) {
                        const int nh = nt >> 1, sub = nt & 1;
                        mma16816(acc[mh * 2 + q][nt], al[q], bb[nh][sub], bb[nh][sub + 2]);
                    }
            }
        }
        __syncthreads();
    }

    const int g  = lane >> 2;
    const int tg = lane & 3;
    #pragma unroll
    for (int mt = 0; mt < 4; mt++) {
        #pragma unroll
        for (int nt = 0; nt < 4; nt++) {
            int n = n_warp + nt * 8 + tg * 2;
            #pragma unroll
            for (int half = 0; half < 2; half++) {
                int m = m0 + m_warp + mt * 16 + g + half * 8;
                float2 v;
                v.x = acc[mt][nt][half * 2 + 0];
                v.y = acc[mt][nt][half * 2 + 1];
                *reinterpret_cast<float2*>(g_H + (size_t)m * HC + n) = v;
            }
        }
    }
}

// ---------------- GEMM2: 1-term fp16, BM=128, BN=128, BK=64, 3-stage ----------------
// Stage layout: Ah @0 (16KB), B @16K (16KB); stage stride 32K. 3 stages = 96KB.
__global__ __launch_bounds__(256, 2)
void gemm2_k(const float* __restrict__ bias, float* __restrict__ Cout) {
    constexpr int KT = 22;
    extern __shared__ __align__(1024) char smem[];
    const uint32_t sb = s2u(smem);
    const int tid = threadIdx.x;
    const int wid = tid >> 5;
    const int lane = tid & 31;
    const int m0 = blockIdx.y * 128;
    const int n0 = blockIdx.x * 128;

    const int wr = wid >> 2;
    const int wc = wid & 3;
    const int m_warp = wr * 64;
    const int n_warp = wc * 32;
    const int lm_row = lane & 15;
    const int lm_kg  = lane >> 4;

    auto load_tile = [&](int s, int it) {
        const int k0 = it * 64;
        const uint32_t st = sb + (uint32_t)s * 32768u;
        #pragma unroll
        for (int r = 0; r < 4; r++) {
            int c = tid + r * 256;
            int row = c >> 3, ch = c & 7;
            uint32_t d = swz((uint32_t)(row * 128 + ch * 16));
            cpa16(st + d,          g_Ah + (size_t)(m0 + row) * KK + k0 + ch * 8);
            cpa16(st + 16384 + d,  g_B  + (size_t)(n0 + row) * KK + k0 + ch * 8);
        }
        cp_commit();
    };

    float acc[4][4][4];
    #pragma unroll
    for (int a = 0; a < 4; a++)
        #pragma unroll
        for (int b = 0; b < 4; b++)
            #pragma unroll
            for (int c = 0; c < 4; c++) acc[a][b][c] = 0.f;

    load_tile(0, 0);
    load_tile(1, 1);

    for (int i = 0; i < KT; i++) {
        const int buf = i % 3;
        if (i + 2 < KT) {
            load_tile((i + 2) % 3, i + 2);
            asm volatile("cp.async.wait_group 2;" ::: "memory");
        } else if (i + 1 < KT) {
            asm volatile("cp.async.wait_group 1;" ::: "memory");
        } else {
            asm volatile("cp.async.wait_group 0;" ::: "memory");
        }
        __syncthreads();

        const uint32_t st = sb + (uint32_t)buf * 32768u;
        #pragma unroll
        for (int ks = 0; ks < 4; ks++) {
            const int kg = ks * 2 + lm_kg;
            uint32_t bb[2][4];
            #pragma unroll
            for (int nh = 0; nh < 2; nh++) {
                uint32_t off = swz((uint32_t)((n_warp + nh * 16 + lm_row) * 128 + kg * 16));
                ldsm4(bb[nh], st + 16384 + off);
            }
            uint32_t ah[4][4];
            #pragma unroll
            for (int mt = 0; mt < 4; mt++) {
                uint32_t off = swz((uint32_t)((m_warp + mt * 16 + lm_row) * 128 + kg * 16));
                ldsm4(ah[mt], st + off);
            }
            #pragma unroll
            for (int mt = 0; mt < 4; mt++)
                #pragma unroll
                for (int nt = 0; nt < 4; nt++) {
                    const int nh = nt >> 1, sub = nt & 1;
                    mma16816(acc[mt][nt], ah[mt], bb[nh][sub], bb[nh][sub + 2]);
                }
        }
        __syncthreads();
    }

    const int g  = lane >> 2;
    const int tg = lane & 3;
    #pragma unroll
    for (int mt = 0; mt < 4; mt++) {
        #pragma unroll
        for (int nt = 0; nt < 4; nt++) {
            int n = n0 + n_warp + nt * 8 + tg * 2;
            float b0 = __ldg(bias + n);
            float b1 = __ldg(bias + n + 1);
            #pragma unroll
            for (int half = 0; half < 2; half++) {
                int m = m0 + m_warp + mt * 16 + g + half * 8;
                float2 v;
                v.x = acc[mt][nt][half * 2 + 0] + b0;
                v.y = acc[mt][nt][half * 2 + 1] + b1;
                *reinterpret_cast<float2*>(Cout + (size_t)m * DOUT + n) = v;
            }
        }
    }
}

// ---------------- host launcher ----------------
extern "C" void kernel_launch(void* const* d_in, const int* in_sizes, int n_in,
                              void* d_out, int out_size) {
    (void)in_sizes; (void)n_in; (void)out_size;
    const float* x         = (const float*)d_in[0];
    const float* base_w    = (const float*)d_in[1];
    const float* base_b    = (const float*)d_in[2];
    const float* shared_w1 = (const float*)d_in[3];
    const float* shared_w2 = (const float*)d_in[4];
    const float* routed_w1 = (const float*)d_in[5];
    const float* routed_w2 = (const float*)d_in[6];
    const float* router_w  = (const float*)d_in[7];
    const float* router_b  = (const float*)d_in[8];

    const int SMEM1 = 98304;  // 2 stages x 48KB
    const int SMEM2 = 98304;  // 3 stages x 32KB
    cudaFuncSetAttribute(gemm1_k, cudaFuncAttributeMaxDynamicSharedMemorySize, SMEM1);
    cudaFuncSetAttribute(gemm2_k, cudaFuncAttributeMaxDynamicSharedMemorySize, SMEM2);

    prep_B<<<dim3(KK / 32, DOUT / 32), dim3(32, 8)>>>(base_w, shared_w2, routed_w2);
    prep_W1<<<(HC * DIN + 255) / 256, 256>>>(shared_w1, routed_w1, router_w);
    split_x<<<(TT * DIN + 255) / 256, 256>>>(x);
    // GEMM1: H[TT,128] = A[:, :1280] @ W1cat  (2-term compensated)
    gemm1_k<<<dim3(1, TT / 128), 256, SMEM1>>>();
    gate_kernel<<<(TT + 255) / 256, 256>>>(router_b);
    // GEMM2: out[TT, DOUT] = Ah[TT, KK] @ Bcat + bias  (1-term fp16)
    gemm2_k<<<dim3(DOUT / 128, TT / 128), 256, SMEM2>>>(base_b, (float*)d_out);
}